// round 1
// baseline (speedup 1.0000x reference)
#include <cuda_runtime.h>
#include <math.h>

#define BB 8
#define LL 2048
#define MM 2048
#define DD 256
#define OD (4*DD)

#define SMEM_PAD 257   // memory tile row stride (floats) -> conflict-free lane-major scalar reads
#define SX_STRIDE 260  // scaled-input row stride (floats), 16B-aligned rows for float4

// Scratch (static device globals: no allocation allowed in kernel_launch)
__device__ float g_indot[BB*LL];
__device__ float g_mbias[BB*MM];
__device__ float g_rowmax[BB*LL];
__device__ float g_gmax[BB];
__device__ float g_Z[BB];
__device__ float g_o2part[BB*8*DD];

// ---------------------------------------------------------------------------
// Kernel A: input_dot[b,l] = input . w_input ; mbias[b,m] = memory . w_memory - 1e30*(1-mask)
// One warp per row, 8 warps per block.
// ---------------------------------------------------------------------------
__global__ void dots_kernel(const float* __restrict__ inp, const float* __restrict__ mem,
                            const float* __restrict__ mask, const float* __restrict__ wi,
                            const float* __restrict__ wm)
{
    int row  = blockIdx.x * 8 + (threadIdx.x >> 5);
    int lane = threadIdx.x & 31;
    bool isMem = row >= BB*LL;
    int r = isMem ? row - BB*LL : row;
    const float* src = (isMem ? mem : inp) + (size_t)r * DD;
    const float* w   = isMem ? wm : wi;

    float s = 0.f;
    #pragma unroll
    for (int k = 0; k < 8; k++) {
        int d = lane + 32*k;
        s = fmaf(src[d], w[d], s);
    }
    #pragma unroll
    for (int off = 16; off; off >>= 1)
        s += __shfl_xor_sync(0xffffffffu, s, off);

    if (lane == 0) {
        if (isMem) g_mbias[r] = s - 1e30f * (1.0f - mask[r]);
        else       g_indot[r] = s;
    }
}

// ---------------------------------------------------------------------------
// Kernel B: fused flash attention (fp32).
// Block = 32 L-rows of one batch; 8 warps x 4 rows each; M tiled by 32.
// Online softmax; also tracks per-row max of att for weight_two.
// Writes out columns [0:3D): input, output_one, input*output_one.
// ---------------------------------------------------------------------------
__global__ void __launch_bounds__(256) flash_kernel(const float* __restrict__ inp,
                                                    const float* __restrict__ mem,
                                                    const float* __restrict__ dscale,
                                                    float* __restrict__ out)
{
    extern __shared__ float sm[];
    float* sMem = sm;                   // [32][SMEM_PAD]
    float* sX   = sm + 32*SMEM_PAD;     // [32][SX_STRIDE]

    const int b       = blockIdx.y;
    const int rowbase = blockIdx.x * 32;
    const int tid     = threadIdx.x;
    const int lane    = tid & 31;
    const int warp    = tid >> 5;

    // Load scaled input rows into sX (once per block)
    {
        int r = tid >> 3;   // 0..31
        int c = tid & 7;    // 0..7
        const float4* xsrc = (const float4*)(inp + ((size_t)(b*LL + rowbase + r)) * DD);
        const float4* dsrc = (const float4*)dscale;
        float4* dst = (float4*)(sX + r * SX_STRIDE);
        #pragma unroll
        for (int j = 0; j < 8; j++) {
            int i4 = c + 8*j;
            float4 x = xsrc[i4];
            float4 s = dsrc[i4];
            x.x *= s.x; x.y *= s.y; x.z *= s.z; x.w *= s.w;
            dst[i4] = x;
        }
    }

    const int row0 = rowbase + warp*4;
    float indot[4];
    #pragma unroll
    for (int r = 0; r < 4; r++) indot[r] = g_indot[b*LL + row0 + r];

    float rmax[4], rsum[4], acc[4][8], p[4];
    #pragma unroll
    for (int r = 0; r < 4; r++) {
        rmax[r] = -INFINITY; rsum[r] = 0.f;
        #pragma unroll
        for (int k = 0; k < 8; k++) acc[r][k] = 0.f;
    }

    for (int t = 0; t < MM/32; ++t) {
        __syncthreads();  // protect sMem from previous tile's readers
        {   // cooperative load of memory tile [32][256] -> sMem
            int r = tid >> 3, c = tid & 7;
            const float4* msrc = (const float4*)(mem + ((size_t)(b*MM + t*32 + r)) * DD);
            float* dst = sMem + r * SMEM_PAD;
            #pragma unroll
            for (int j = 0; j < 8; j++) {
                int i4 = c + 8*j;
                float4 v = msrc[i4];
                dst[4*i4+0] = v.x; dst[4*i4+1] = v.y; dst[4*i4+2] = v.z; dst[4*i4+3] = v.w;
            }
        }
        __syncthreads();

        float mb = g_mbias[b*MM + t*32 + lane];

        // scores: s[r] = dot(xscaled[row r], mem[m=lane])   (lane <-> m)
        float a[4] = {0.f, 0.f, 0.f, 0.f};
        {
            const float* mp = sMem + lane * SMEM_PAD;
            const float4* x0 = (const float4*)(sX + (warp*4+0) * SX_STRIDE);
            const float4* x1 = (const float4*)(sX + (warp*4+1) * SX_STRIDE);
            const float4* x2 = (const float4*)(sX + (warp*4+2) * SX_STRIDE);
            const float4* x3 = (const float4*)(sX + (warp*4+3) * SX_STRIDE);
            #pragma unroll 8
            for (int j = 0; j < 64; j++) {
                float m0 = mp[4*j+0], m1 = mp[4*j+1], m2 = mp[4*j+2], m3 = mp[4*j+3];
                float4 v;
                v = x0[j]; a[0] = fmaf(v.x,m0, fmaf(v.y,m1, fmaf(v.z,m2, fmaf(v.w,m3, a[0]))));
                v = x1[j]; a[1] = fmaf(v.x,m0, fmaf(v.y,m1, fmaf(v.z,m2, fmaf(v.w,m3, a[1]))));
                v = x2[j]; a[2] = fmaf(v.x,m0, fmaf(v.y,m1, fmaf(v.z,m2, fmaf(v.w,m3, a[2]))));
                v = x3[j]; a[3] = fmaf(v.x,m0, fmaf(v.y,m1, fmaf(v.z,m2, fmaf(v.w,m3, a[3]))));
            }
        }

        // online softmax update per row
        #pragma unroll
        for (int r = 0; r < 4; r++) {
            float sv = a[r] + indot[r] + mb;
            float tm = sv;
            #pragma unroll
            for (int o = 16; o; o >>= 1) tm = fmaxf(tm, __shfl_xor_sync(0xffffffffu, tm, o));
            float nmax = fmaxf(rmax[r], tm);
            float corr = expf(rmax[r] - nmax);   // exp(-inf)=0 on first tile
            float pv   = expf(sv - nmax);
            float ps   = pv;
            #pragma unroll
            for (int o = 16; o; o >>= 1) ps += __shfl_xor_sync(0xffffffffu, ps, o);
            rsum[r] = rsum[r] * corr + ps;
            rmax[r] = nmax;
            #pragma unroll
            for (int k = 0; k < 8; k++) acc[r][k] *= corr;
            p[r] = pv;
        }

        // PV: acc[r][k] += sum_m p[r][m] * mem[m][d=lane+32k]
        for (int mm = 0; mm < 32; ++mm) {
            float q0 = __shfl_sync(0xffffffffu, p[0], mm);
            float q1 = __shfl_sync(0xffffffffu, p[1], mm);
            float q2 = __shfl_sync(0xffffffffu, p[2], mm);
            float q3 = __shfl_sync(0xffffffffu, p[3], mm);
            const float* mp2 = sMem + mm * SMEM_PAD + lane;
            #pragma unroll
            for (int k = 0; k < 8; k++) {
                float mv = mp2[32*k];
                acc[0][k] = fmaf(q0, mv, acc[0][k]);
                acc[1][k] = fmaf(q1, mv, acc[1][k]);
                acc[2][k] = fmaf(q2, mv, acc[2][k]);
                acc[3][k] = fmaf(q3, mv, acc[3][k]);
            }
        }
    }

    // epilogue: normalize, write cols [0:3D), store row maxima
    #pragma unroll
    for (int r = 0; r < 4; r++) {
        int row = row0 + r;
        float inv = 1.0f / rsum[r];
        size_t ob = ((size_t)(b*LL + row)) * OD;
        const float* xi = inp + ((size_t)(b*LL + row)) * DD;
        #pragma unroll
        for (int k = 0; k < 8; k++) {
            int d = lane + 32*k;
            float o1 = acc[r][k] * inv;
            float xv = xi[d];
            out[ob + d]        = xv;
            out[ob + DD + d]   = o1;
            out[ob + 2*DD + d] = xv * o1;
        }
        if (lane == 0) g_rowmax[b*LL + row] = rmax[r];
    }
}

// ---------------------------------------------------------------------------
// Kernel C0: per-batch max & softmax denominator over L of rowmax
// ---------------------------------------------------------------------------
__global__ void c0_kernel()
{
    int b = blockIdx.x, tid = threadIdx.x;
    __shared__ float red[256];
    float m = -INFINITY;
    for (int l = tid; l < LL; l += 256) m = fmaxf(m, g_rowmax[b*LL + l]);
    red[tid] = m; __syncthreads();
    for (int s = 128; s; s >>= 1) { if (tid < s) red[tid] = fmaxf(red[tid], red[tid+s]); __syncthreads(); }
    float gmax = red[0]; __syncthreads();
    float z = 0.f;
    for (int l = tid; l < LL; l += 256) z += expf(g_rowmax[b*LL + l] - gmax);
    red[tid] = z; __syncthreads();
    for (int s = 128; s; s >>= 1) { if (tid < s) red[tid] += red[tid+s]; __syncthreads(); }
    if (tid == 0) { g_gmax[b] = gmax; g_Z[b] = red[0]; }
}

// ---------------------------------------------------------------------------
// Kernel C1: partial output_two over an L-slice of 256 (deterministic, no atomics)
// ---------------------------------------------------------------------------
__global__ void c1_kernel(const float* __restrict__ inp)
{
    int b = blockIdx.y, sblk = blockIdx.x, tid = threadIdx.x;
    __shared__ float ws[256];
    float gmax = g_gmax[b], invZ = 1.0f / g_Z[b];
    int l0 = sblk * 256;
    ws[tid] = expf(g_rowmax[b*LL + l0 + tid] - gmax) * invZ;
    __syncthreads();
    float acc = 0.f;
    const float* xp = inp + ((size_t)b*LL + l0) * DD + tid;
    #pragma unroll 4
    for (int l = 0; l < 256; l++) acc = fmaf(ws[l], xp[(size_t)l * DD], acc);
    g_o2part[(b*8 + sblk)*DD + tid] = acc;
}

// ---------------------------------------------------------------------------
// Kernel C2: finalize output_two, write col [3D:4D) = output_two * output_one
// ---------------------------------------------------------------------------
__global__ void c2_kernel(float* __restrict__ out)
{
    int b = blockIdx.y, tid = threadIdx.x;
    __shared__ float o2s[256];
    float a = 0.f;
    #pragma unroll
    for (int s = 0; s < 8; s++) a += g_o2part[(b*8 + s)*DD + tid];
    o2s[tid] = a; __syncthreads();
    int lbase = blockIdx.x * 16;
    for (int rr = 0; rr < 16; rr++) {
        size_t ob = ((size_t)(b*LL + lbase + rr)) * OD;
        out[ob + 3*DD + tid] = o2s[tid] * out[ob + DD + tid];
    }
}

// ---------------------------------------------------------------------------
extern "C" void kernel_launch(void* const* d_in, const int* in_sizes, int n_in,
                              void* d_out, int out_size)
{
    const float* inp  = (const float*)d_in[0];
    const float* mem  = (const float*)d_in[1];
    const float* mask = (const float*)d_in[2];
    const float* wi   = (const float*)d_in[3];
    const float* wm   = (const float*)d_in[4];
    const float* ds   = (const float*)d_in[5];
    float* out = (float*)d_out;

    const size_t SMEM = (size_t)(32*SMEM_PAD + 32*SX_STRIDE) * sizeof(float); // 66176 B
    cudaFuncSetAttribute(flash_kernel, cudaFuncAttributeMaxDynamicSharedMemorySize, (int)SMEM);

    dots_kernel<<<(BB*(LL+MM))/8, 256>>>(inp, mem, mask, wi, wm);
    flash_kernel<<<dim3(LL/32, BB), 256, SMEM>>>(inp, mem, ds, out);
    c0_kernel<<<BB, 256>>>();
    c1_kernel<<<dim3(LL/256, BB), 256>>>(inp);
    c2_kernel<<<dim3(LL/16, BB), 256>>>(out);
}

// round 3
// speedup vs baseline: 2.4069x; 2.4069x over previous
#include <cuda_runtime.h>
#include <cuda_bf16.h>
#include <math.h>
#include <stdint.h>

#define BB 8
#define LL 2048
#define MM 2048
#define DD 256
#define OD 1024

// ---------------------------------------------------------------------------
// Scratch (device globals; no allocation allowed)
// ---------------------------------------------------------------------------
__device__ float g_att[(size_t)BB * LL * MM];        // 134 MB
__device__ float g_indot[BB*LL], g_mbias[BB*MM];
__device__ float g_rowmax[BB*LL], g_rowinv[BB*LL];
__device__ float g_gmax[BB], g_Z[BB], g_o2part[BB*8*DD];

// ---------------------------------------------------------------------------
// PTX helpers: ldmatrix + mma.sync (generic-target-safe, sm_80+ PTX)
// ---------------------------------------------------------------------------
__device__ __forceinline__ uint32_t smem_u32(const void* p) {
    uint32_t a;
    asm("{ .reg .u64 t; cvta.to.shared.u64 t, %1; cvt.u32.u64 %0, t; }" : "=r"(a) : "l"(p));
    return a;
}
__device__ __forceinline__ void ldsm_x4(uint32_t* r, uint32_t a) {
    asm volatile("ldmatrix.sync.aligned.m8n8.x4.shared.b16 {%0,%1,%2,%3}, [%4];"
        : "=r"(r[0]), "=r"(r[1]), "=r"(r[2]), "=r"(r[3]) : "r"(a));
}
__device__ __forceinline__ void ldsm_x2(uint32_t* r, uint32_t a) {
    asm volatile("ldmatrix.sync.aligned.m8n8.x2.shared.b16 {%0,%1}, [%2];"
        : "=r"(r[0]), "=r"(r[1]) : "r"(a));
}
__device__ __forceinline__ void ldsm_x2t(uint32_t* r, uint32_t a) {
    asm volatile("ldmatrix.sync.aligned.m8n8.x2.trans.shared.b16 {%0,%1}, [%2];"
        : "=r"(r[0]), "=r"(r[1]) : "r"(a));
}
__device__ __forceinline__ void mma16816(float* d, const uint32_t* a, const uint32_t* b) {
    asm volatile("mma.sync.aligned.m16n8k16.row.col.f32.bf16.bf16.f32 "
        "{%0,%1,%2,%3}, {%4,%5,%6,%7}, {%8,%9}, {%0,%1,%2,%3};"
        : "+f"(d[0]), "+f"(d[1]), "+f"(d[2]), "+f"(d[3])
        : "r"(a[0]), "r"(a[1]), "r"(a[2]), "r"(a[3]), "r"(b[0]), "r"(b[1]));
}

// split 4 floats into hi/lo bf16 pairs (packed 2 per u32)
__device__ __forceinline__ void split4(float4 v, uint2& hi, uint2& lo) {
    __nv_bfloat16 h0 = __float2bfloat16(v.x), h1 = __float2bfloat16(v.y);
    __nv_bfloat16 h2 = __float2bfloat16(v.z), h3 = __float2bfloat16(v.w);
    __nv_bfloat16 l0 = __float2bfloat16(v.x - __bfloat162float(h0));
    __nv_bfloat16 l1 = __float2bfloat16(v.y - __bfloat162float(h1));
    __nv_bfloat16 l2 = __float2bfloat16(v.z - __bfloat162float(h2));
    __nv_bfloat16 l3 = __float2bfloat16(v.w - __bfloat162float(h3));
    hi.x = (uint32_t)__bfloat16_as_ushort(h0) | ((uint32_t)__bfloat16_as_ushort(h1) << 16);
    hi.y = (uint32_t)__bfloat16_as_ushort(h2) | ((uint32_t)__bfloat16_as_ushort(h3) << 16);
    lo.x = (uint32_t)__bfloat16_as_ushort(l0) | ((uint32_t)__bfloat16_as_ushort(l1) << 16);
    lo.y = (uint32_t)__bfloat16_as_ushort(l2) | ((uint32_t)__bfloat16_as_ushort(l3) << 16);
}

// ---------------------------------------------------------------------------
// smem layout constants
// ---------------------------------------------------------------------------
#define STRA  72   // A/B1 tile row stride in halves (128 rows x 64 k, padded)
#define STRB2 136  // GEMM2 B tile row stride in halves (64 k-rows x 128 n, padded)

#define G1_SA_HI 0
#define G1_SA_LO 18432
#define G1_SB_HI 36864
#define G1_SB_LO 55296
#define G1_INDOT 73728
#define G1_MBIAS 74240
#define G1_SMEM  74752

#define G2_SA_HI 0
#define G2_SA_LO 18432
#define G2_SB_HI 36864
#define G2_SB_LO 54272
#define G2_RMAX  71680
#define G2_RINV  72192
#define G2_SMEM  72704

// ---------------------------------------------------------------------------
// dots: indot[b,l] = input.w_input ; mbias[b,m] = memory.w_memory - 1e30*(1-mask)
// ---------------------------------------------------------------------------
__global__ void dots_kernel(const float* __restrict__ inp, const float* __restrict__ mem,
                            const float* __restrict__ mask, const float* __restrict__ wi,
                            const float* __restrict__ wm) {
    int row = blockIdx.x * 8 + (threadIdx.x >> 5);
    int lane = threadIdx.x & 31;
    bool isMem = row >= BB * LL;
    int r = isMem ? row - BB * LL : row;
    const float* src = (isMem ? mem : inp) + (size_t)r * DD;
    const float* w = isMem ? wm : wi;
    float s = 0.f;
    #pragma unroll
    for (int k = 0; k < 8; k++) { int d = lane + 32 * k; s = fmaf(src[d], w[d], s); }
    #pragma unroll
    for (int o = 16; o; o >>= 1) s += __shfl_xor_sync(0xffffffffu, s, o);
    if (lane == 0) {
        if (isMem) g_mbias[r] = s - 1e30f * (1.0f - mask[r]);
        else       g_indot[r] = s;
    }
}

// ---------------------------------------------------------------------------
// GEMM1: att[b,l,m] = (inp*ds).mem^T + indot + mbias    (HMMA bf16x3)
// grid (L/128, M/128, B), 256 thr, warp tile 32x64
// ---------------------------------------------------------------------------
__global__ void __launch_bounds__(256) gemm1_kernel(const float* __restrict__ inp,
                                                    const float* __restrict__ mem,
                                                    const float* __restrict__ ds) {
    extern __shared__ char sm[];
    const uint32_t s0 = smem_u32(sm);
    const int tid = threadIdx.x, lane = tid & 31, warp = tid >> 5;
    const int lbase = blockIdx.x * 128, nbase = blockIdx.y * 128, b = blockIdx.z;

    float* sIndot = (float*)(sm + G1_INDOT);
    float* sMbias = (float*)(sm + G1_MBIAS);
    if (tid < 128) {
        sIndot[tid] = g_indot[b * LL + lbase + tid];
        sMbias[tid] = g_mbias[b * MM + nbase + tid];
    }

    const float* Ag = inp + (size_t)(b * LL + lbase) * DD;
    const float* Bg = mem + (size_t)(b * MM + nbase) * DD;

    float acc[2][8][4];
    #pragma unroll
    for (int mt = 0; mt < 2; mt++)
        #pragma unroll
        for (int nt = 0; nt < 8; nt++)
            #pragma unroll
            for (int q = 0; q < 4; q++) acc[mt][nt][q] = 0.f;

    const int warpM = (warp >> 1) * 32, warpN = (warp & 1) * 64;
    const int g = lane >> 3, lr = lane & 7, h = (lane >> 3) & 1;

    for (int kc = 0; kc < 4; kc++) {
        __syncthreads();
        #pragma unroll
        for (int it = 0; it < 8; it++) {
            int i = tid + it * 256;           // 0..2047
            int row = i >> 4, c4 = i & 15;
            int kk = kc * 64 + c4 * 4;
            uint32_t soff = (uint32_t)(row * STRA + c4 * 4) * 2;
            float4 v = *(const float4*)(Ag + (size_t)row * DD + kk);
            float4 sc = *(const float4*)(ds + kk);
            v.x *= sc.x; v.y *= sc.y; v.z *= sc.z; v.w *= sc.w;
            uint2 hi, lo;
            split4(v, hi, lo);
            *(uint2*)(sm + G1_SA_HI + soff) = hi;
            *(uint2*)(sm + G1_SA_LO + soff) = lo;
            float4 w = *(const float4*)(Bg + (size_t)row * DD + kk);
            split4(w, hi, lo);
            *(uint2*)(sm + G1_SB_HI + soff) = hi;
            *(uint2*)(sm + G1_SB_LO + soff) = lo;
        }
        __syncthreads();

        #pragma unroll
        for (int ks = 0; ks < 4; ks++) {
            uint32_t aoff = s0 + 2u * ((warpM + (g & 1) * 8 + lr) * STRA + ks * 16 + (g >> 1) * 8);
            uint32_t boff = s0 + 2u * ((warpN + lr) * STRA + ks * 16 + h * 8);
            uint32_t ah[2][4], al[2][4], bh[8][2], bl[8][2];
            ldsm_x4(ah[0], aoff + G1_SA_HI);
            ldsm_x4(ah[1], aoff + G1_SA_HI + 16 * STRA * 2);
            #pragma unroll
            for (int nt = 0; nt < 8; nt++) ldsm_x2(bh[nt], boff + G1_SB_HI + nt * 8 * STRA * 2);
            #pragma unroll
            for (int mt = 0; mt < 2; mt++)
                #pragma unroll
                for (int nt = 0; nt < 8; nt++) mma16816(acc[mt][nt], ah[mt], bh[nt]);
            #pragma unroll
            for (int nt = 0; nt < 8; nt++) ldsm_x2(bl[nt], boff + G1_SB_LO + nt * 8 * STRA * 2);
            #pragma unroll
            for (int mt = 0; mt < 2; mt++)
                #pragma unroll
                for (int nt = 0; nt < 8; nt++) mma16816(acc[mt][nt], ah[mt], bl[nt]);
            ldsm_x4(al[0], aoff + G1_SA_LO);
            ldsm_x4(al[1], aoff + G1_SA_LO + 16 * STRA * 2);
            #pragma unroll
            for (int mt = 0; mt < 2; mt++)
                #pragma unroll
                for (int nt = 0; nt < 8; nt++) mma16816(acc[mt][nt], al[mt], bh[nt]);
        }
    }

    // epilogue: att = acc + indot[row] + mbias[col]
    const int r0 = lane >> 2, c0 = 2 * (lane & 3);
    #pragma unroll
    for (int mt = 0; mt < 2; mt++) {
        #pragma unroll
        for (int nt = 0; nt < 8; nt++) {
            int lrow = warpM + mt * 16 + r0;
            int lcol = warpN + nt * 8 + c0;
            float bi0 = sMbias[lcol], bi1 = sMbias[lcol + 1];
            size_t base = ((size_t)(b * LL + lbase + lrow)) * MM + nbase + lcol;
            float2 v0 = make_float2(acc[mt][nt][0] + sIndot[lrow] + bi0,
                                    acc[mt][nt][1] + sIndot[lrow] + bi1);
            float2 v1 = make_float2(acc[mt][nt][2] + sIndot[lrow + 8] + bi0,
                                    acc[mt][nt][3] + sIndot[lrow + 8] + bi1);
            *(float2*)(g_att + base) = v0;
            *(float2*)(g_att + base + 8 * MM) = v1;
        }
    }
}

// ---------------------------------------------------------------------------
// rowstat: per (b,l) row of att -> max, 1/sum(exp)
// ---------------------------------------------------------------------------
__global__ void rowstat_kernel() {
    int row = blockIdx.x, tid = threadIdx.x;
    const float* p = g_att + (size_t)row * MM;
    float v[8]; float m = -INFINITY;
    #pragma unroll
    for (int j = 0; j < 8; j++) { v[j] = p[tid + 256 * j]; m = fmaxf(m, v[j]); }
    __shared__ float red[256];
    red[tid] = m; __syncthreads();
    for (int s = 128; s; s >>= 1) { if (tid < s) red[tid] = fmaxf(red[tid], red[tid + s]); __syncthreads(); }
    float bmax = red[0]; __syncthreads();
    float ss = 0.f;
    #pragma unroll
    for (int j = 0; j < 8; j++) ss += __expf(v[j] - bmax);
    red[tid] = ss; __syncthreads();
    for (int s = 128; s; s >>= 1) { if (tid < s) red[tid] += red[tid + s]; __syncthreads(); }
    if (tid == 0) { g_rowmax[row] = bmax; g_rowinv[row] = 1.0f / red[0]; }
}

// ---------------------------------------------------------------------------
// GEMM2: output_one = softmax(att).mem   (HMMA bf16x3, inline exp, trans-B)
// grid (L/128, D/128, B). Writes out cols [0:768).
// ---------------------------------------------------------------------------
__global__ void __launch_bounds__(256) gemm2_kernel(const float* __restrict__ inp,
                                                    const float* __restrict__ mem,
                                                    float* __restrict__ out) {
    extern __shared__ char sm[];
    const uint32_t s0 = smem_u32(sm);
    const int tid = threadIdx.x, lane = tid & 31, warp = tid >> 5;
    const int lbase = blockIdx.x * 128, dbase = blockIdx.y * 128, b = blockIdx.z;

    float* sRmax = (float*)(sm + G2_RMAX);
    float* sRinv = (float*)(sm + G2_RINV);
    if (tid < 128) {
        sRmax[tid] = g_rowmax[b * LL + lbase + tid];
        sRinv[tid] = g_rowinv[b * LL + lbase + tid];
    }

    float acc[2][8][4];
    #pragma unroll
    for (int mt = 0; mt < 2; mt++)
        #pragma unroll
        for (int nt = 0; nt < 8; nt++)
            #pragma unroll
            for (int q = 0; q < 4; q++) acc[mt][nt][q] = 0.f;

    const int warpM = (warp >> 1) * 32, warpN = (warp & 1) * 64;
    const int g = lane >> 3, lr = lane & 7, h = (lane >> 3) & 1;
    const float* attBase = g_att + ((size_t)(b * LL + lbase)) * MM;

    for (int kc = 0; kc < 32; kc++) {
        __syncthreads();
        // A: 128 L-rows x 64 m, inline softmax weight
        #pragma unroll
        for (int it = 0; it < 8; it++) {
            int i = tid + it * 256;
            int row = i >> 4, c4 = i & 15;
            int mm0 = kc * 64 + c4 * 4;
            float4 v = *(const float4*)(attBase + (size_t)row * MM + mm0);
            float mx = sRmax[row], iz = sRinv[row];
            v.x = __expf(v.x - mx) * iz; v.y = __expf(v.y - mx) * iz;
            v.z = __expf(v.z - mx) * iz; v.w = __expf(v.w - mx) * iz;
            uint2 hi, lo;
            split4(v, hi, lo);
            uint32_t soff = (uint32_t)(row * STRA + c4 * 4) * 2;
            *(uint2*)(sm + G2_SA_HI + soff) = hi;
            *(uint2*)(sm + G2_SA_LO + soff) = lo;
        }
        // B: 64 m-rows x 128 d (k-major rows, n contiguous -> trans ldmatrix later)
        #pragma unroll
        for (int it = 0; it < 8; it++) {
            int i = tid + it * 256;
            int row = i >> 5, c4 = i & 31;
            float4 v = *(const float4*)(mem + ((size_t)(b * MM + kc * 64 + row)) * DD + dbase + c4 * 4);
            uint2 hi, lo;
            split4(v, hi, lo);
            uint32_t soff = (uint32_t)(row * STRB2 + c4 * 4) * 2;
            *(uint2*)(sm + G2_SB_HI + soff) = hi;
            *(uint2*)(sm + G2_SB_LO + soff) = lo;
        }
        __syncthreads();

        #pragma unroll
        for (int ks = 0; ks < 4; ks++) {
            uint32_t aoff = s0 + 2u * ((warpM + (g & 1) * 8 + lr) * STRA + ks * 16 + (g >> 1) * 8);
            int kk = ks * 16 + h * 8 + lr;
            uint32_t boff = s0 + 2u * (kk * STRB2 + warpN);
            uint32_t ah[2][4], al[2][4], bh[8][2], bl[8][2];
            ldsm_x4(ah[0], aoff + G2_SA_HI);
            ldsm_x4(ah[1], aoff + G2_SA_HI + 16 * STRA * 2);
            #pragma unroll
            for (int nt = 0; nt < 8; nt++) ldsm_x2t(bh[nt], boff + G2_SB_HI + nt * 16);
            #pragma unroll
            for (int mt = 0; mt < 2; mt++)
                #pragma unroll
                for (int nt = 0; nt < 8; nt++) mma16816(acc[mt][nt], ah[mt], bh[nt]);
            #pragma unroll
            for (int nt = 0; nt < 8; nt++) ldsm_x2t(bl[nt], boff + G2_SB_LO + nt * 16);
            #pragma unroll
            for (int mt = 0; mt < 2; mt++)
                #pragma unroll
                for (int nt = 0; nt < 8; nt++) mma16816(acc[mt][nt], ah[mt], bl[nt]);
            ldsm_x4(al[0], aoff + G2_SA_LO);
            ldsm_x4(al[1], aoff + G2_SA_LO + 16 * STRA * 2);
            #pragma unroll
            for (int mt = 0; mt < 2; mt++)
                #pragma unroll
                for (int nt = 0; nt < 8; nt++) mma16816(acc[mt][nt], al[mt], bh[nt]);
        }
    }

    // epilogue: write input / output_one / input*output_one
    const int r0 = lane >> 2, c0 = 2 * (lane & 3);
    #pragma unroll
    for (int mt = 0; mt < 2; mt++) {
        #pragma unroll
        for (int nt = 0; nt < 8; nt++) {
            int lrow = warpM + mt * 16 + r0;
            int d = dbase + warpN + nt * 8 + c0;
            #pragma unroll
            for (int half = 0; half < 2; half++) {
                size_t grow = (size_t)(b * LL + lbase + lrow + half * 8);
                float2 xv = *(const float2*)(inp + grow * DD + d);
                float2 o1 = make_float2(acc[mt][nt][half * 2], acc[mt][nt][half * 2 + 1]);
                float* ob = out + grow * OD;
                *(float2*)(ob + d)          = xv;
                *(float2*)(ob + DD + d)     = o1;
                *(float2*)(ob + 2 * DD + d) = make_float2(xv.x * o1.x, xv.y * o1.y);
            }
        }
    }
}

// ---------------------------------------------------------------------------
// output_two path
// ---------------------------------------------------------------------------
__global__ void c0_kernel() {
    int b = blockIdx.x, tid = threadIdx.x;
    __shared__ float red[256];
    float m = -INFINITY;
    for (int l = tid; l < LL; l += 256) m = fmaxf(m, g_rowmax[b * LL + l]);
    red[tid] = m; __syncthreads();
    for (int s = 128; s; s >>= 1) { if (tid < s) red[tid] = fmaxf(red[tid], red[tid + s]); __syncthreads(); }
    float gmax = red[0]; __syncthreads();
    float z = 0.f;
    for (int l = tid; l < LL; l += 256) z += expf(g_rowmax[b * LL + l] - gmax);
    red[tid] = z; __syncthreads();
    for (int s = 128; s; s >>= 1) { if (tid < s) red[tid] += red[tid + s]; __syncthreads(); }
    if (tid == 0) { g_gmax[b] = gmax; g_Z[b] = red[0]; }
}

__global__ void c1_kernel(const float* __restrict__ inp) {
    int b = blockIdx.y, sblk = blockIdx.x, tid = threadIdx.x;
    __shared__ float ws[256];
    float gmax = g_gmax[b], invZ = 1.0f / g_Z[b];
    int l0 = sblk * 256;
    ws[tid] = expf(g_rowmax[b * LL + l0 + tid] - gmax) * invZ;
    __syncthreads();
    float acc = 0.f;
    const float* xp = inp + ((size_t)b * LL + l0) * DD + tid;
    #pragma unroll 4
    for (int l = 0; l < 256; l++) acc = fmaf(ws[l], xp[(size_t)l * DD], acc);
    g_o2part[(b * 8 + sblk) * DD + tid] = acc;
}

__global__ void c2_kernel(float* __restrict__ out) {
    int b = blockIdx.y, tid = threadIdx.x;
    __shared__ float o2s[256];
    float a = 0.f;
    #pragma unroll
    for (int s = 0; s < 8; s++) a += g_o2part[(b * 8 + s) * DD + tid];
    o2s[tid] = a; __syncthreads();
    int lbase = blockIdx.x * 16;
    for (int rr = 0; rr < 16; rr++) {
        size_t ob = ((size_t)(b * LL + lbase + rr)) * OD;
        out[ob + 3 * DD + tid] = o2s[tid] * out[ob + DD + tid];
    }
}

// ---------------------------------------------------------------------------
extern "C" void kernel_launch(void* const* d_in, const int* in_sizes, int n_in,
                              void* d_out, int out_size) {
    const float* inp  = (const float*)d_in[0];
    const float* mem  = (const float*)d_in[1];
    const float* mask = (const float*)d_in[2];
    const float* wi   = (const float*)d_in[3];
    const float* wm   = (const float*)d_in[4];
    const float* ds   = (const float*)d_in[5];
    float* out = (float*)d_out;

    cudaFuncSetAttribute(gemm1_kernel, cudaFuncAttributeMaxDynamicSharedMemorySize, G1_SMEM);
    cudaFuncSetAttribute(gemm2_kernel, cudaFuncAttributeMaxDynamicSharedMemorySize, G2_SMEM);

    dots_kernel<<<(BB * (LL + MM)) / 8, 256>>>(inp, mem, mask, wi, wm);
    gemm1_kernel<<<dim3(LL / 128, MM / 128, BB), 256, G1_SMEM>>>(inp, mem, ds);
    rowstat_kernel<<<BB * LL, 256>>>();
    gemm2_kernel<<<dim3(LL / 128, DD / 128, BB), 256, G2_SMEM>>>(inp, mem, out);
    c0_kernel<<<BB, 256>>>();
    c1_kernel<<<dim3(LL / 256, BB), 256>>>(inp);
    c2_kernel<<<dim3(LL / 16, BB), 256>>>(out);
}

// round 4
// speedup vs baseline: 3.5339x; 1.4683x over previous
#include <cuda_runtime.h>
#include <cuda_bf16.h>
#include <math.h>
#include <stdint.h>

#define BB 8
#define LL 2048
#define MM 2048
#define DD 256
#define OD 1024

// ---------------------------------------------------------------------------
// Scratch (device globals)
// ---------------------------------------------------------------------------
__device__ float g_att[(size_t)BB * LL * MM];                 // 134 MB
__device__ __nv_bfloat16 g_xs_hi[BB*LL*DD],  g_xs_lo[BB*LL*DD];
__device__ __nv_bfloat16 g_mem_hi[BB*MM*DD], g_mem_lo[BB*MM*DD];
__device__ float g_indot[BB*LL], g_mbias[BB*MM];
__device__ float g_pmax[BB*LL*16], g_psum[BB*LL*16];
__device__ float g_rowmax[BB*LL], g_rowinv[BB*LL];
__device__ float g_gmax[BB], g_Z[BB], g_o2part[BB*8*DD];

// ---------------------------------------------------------------------------
// PTX helpers (generic-target-safe: ldmatrix + mma.sync, sm_80 PTX)
// ---------------------------------------------------------------------------
__device__ __forceinline__ uint32_t smem_u32(const void* p) {
    uint32_t a;
    asm("{ .reg .u64 t; cvta.to.shared.u64 t, %1; cvt.u32.u64 %0, t; }" : "=r"(a) : "l"(p));
    return a;
}
__device__ __forceinline__ void ldsm_x4(uint32_t* r, uint32_t a) {
    asm volatile("ldmatrix.sync.aligned.m8n8.x4.shared.b16 {%0,%1,%2,%3}, [%4];"
        : "=r"(r[0]), "=r"(r[1]), "=r"(r[2]), "=r"(r[3]) : "r"(a));
}
__device__ __forceinline__ void ldsm_x2(uint32_t* r, uint32_t a) {
    asm volatile("ldmatrix.sync.aligned.m8n8.x2.shared.b16 {%0,%1}, [%2];"
        : "=r"(r[0]), "=r"(r[1]) : "r"(a));
}
__device__ __forceinline__ void ldsm_x2t(uint32_t* r, uint32_t a) {
    asm volatile("ldmatrix.sync.aligned.m8n8.x2.trans.shared.b16 {%0,%1}, [%2];"
        : "=r"(r[0]), "=r"(r[1]) : "r"(a));
}
__device__ __forceinline__ void mma16816(float* d, const uint32_t* a, const uint32_t* b) {
    asm volatile("mma.sync.aligned.m16n8k16.row.col.f32.bf16.bf16.f32 "
        "{%0,%1,%2,%3}, {%4,%5,%6,%7}, {%8,%9}, {%0,%1,%2,%3};"
        : "+f"(d[0]), "+f"(d[1]), "+f"(d[2]), "+f"(d[3])
        : "r"(a[0]), "r"(a[1]), "r"(a[2]), "r"(a[3]), "r"(b[0]), "r"(b[1]));
}
__device__ __forceinline__ void split4(float4 v, uint2& hi, uint2& lo) {
    __nv_bfloat16 h0 = __float2bfloat16(v.x), h1 = __float2bfloat16(v.y);
    __nv_bfloat16 h2 = __float2bfloat16(v.z), h3 = __float2bfloat16(v.w);
    __nv_bfloat16 l0 = __float2bfloat16(v.x - __bfloat162float(h0));
    __nv_bfloat16 l1 = __float2bfloat16(v.y - __bfloat162float(h1));
    __nv_bfloat16 l2 = __float2bfloat16(v.z - __bfloat162float(h2));
    __nv_bfloat16 l3 = __float2bfloat16(v.w - __bfloat162float(h3));
    hi.x = (uint32_t)__bfloat16_as_ushort(h0) | ((uint32_t)__bfloat16_as_ushort(h1) << 16);
    hi.y = (uint32_t)__bfloat16_as_ushort(h2) | ((uint32_t)__bfloat16_as_ushort(h3) << 16);
    lo.x = (uint32_t)__bfloat16_as_ushort(l0) | ((uint32_t)__bfloat16_as_ushort(l1) << 16);
    lo.y = (uint32_t)__bfloat16_as_ushort(l2) | ((uint32_t)__bfloat16_as_ushort(l3) << 16);
}

// ---------------------------------------------------------------------------
// smem layout
// ---------------------------------------------------------------------------
#define STRA  72    // A/B1 row stride in halves (rows x 64 k)
#define STRB2 264   // GEMM2 B row stride in halves (64 k-rows x 256 n + pad)

#define G1_SA_HI 0
#define G1_SA_LO 18432
#define G1_SB_HI 36864
#define G1_SB_LO 55296
#define G1_INDOT 73728
#define G1_MBIAS 74240
#define G1_PMAX  74752
#define G1_PSUM  75776
#define G1_SMEM  76800

#define G2_SA_HI 0
#define G2_SA_LO 9216
#define G2_SB_HI 18432
#define G2_SB_LO 52224
#define G2_RMAX  86016
#define G2_RINV  86272
#define G2_SMEM  86528

// ---------------------------------------------------------------------------
// dots
// ---------------------------------------------------------------------------
__global__ void dots_kernel(const float* __restrict__ inp, const float* __restrict__ mem,
                            const float* __restrict__ mask, const float* __restrict__ wi,
                            const float* __restrict__ wm) {
    int row = blockIdx.x * 8 + (threadIdx.x >> 5);
    int lane = threadIdx.x & 31;
    bool isMem = row >= BB * LL;
    int r = isMem ? row - BB * LL : row;
    const float* src = (isMem ? mem : inp) + (size_t)r * DD;
    const float* w = isMem ? wm : wi;
    float s = 0.f;
    #pragma unroll
    for (int k = 0; k < 8; k++) { int d = lane + 32 * k; s = fmaf(src[d], w[d], s); }
    #pragma unroll
    for (int o = 16; o; o >>= 1) s += __shfl_xor_sync(0xffffffffu, s, o);
    if (lane == 0) {
        if (isMem) g_mbias[r] = s - 1e30f * (1.0f - mask[r]);
        else       g_indot[r] = s;
    }
}

// ---------------------------------------------------------------------------
// conv: hi/lo bf16 split of xs = input*ds and memory
// ---------------------------------------------------------------------------
__global__ void conv_kernel(const float* __restrict__ inp, const float* __restrict__ mem,
                            const float* __restrict__ ds) {
    const int N4 = BB * LL * DD / 4;
    int i = blockIdx.x * 256 + threadIdx.x;
    bool isMem = i >= N4;
    int j = isMem ? i - N4 : i;
    float4 x = ((const float4*)(isMem ? mem : inp))[j];
    if (!isMem) {
        float4 s = ((const float4*)ds)[j & (DD / 4 - 1)];
        x.x *= s.x; x.y *= s.y; x.z *= s.z; x.w *= s.w;
    }
    uint2 hv, lv;
    split4(x, hv, lv);
    ((uint2*)(isMem ? g_mem_hi : g_xs_hi))[j] = hv;
    ((uint2*)(isMem ? g_mem_lo : g_xs_lo))[j] = lv;
}

// ---------------------------------------------------------------------------
// GEMM1: att = xs.mem^T + indot + mbias, plus partial row max/sumexp
// grid (L/128, M/128, B); warp tile 32x64 (4M x 2N warps)
// ---------------------------------------------------------------------------
__global__ void __launch_bounds__(256) gemm1_kernel() {
    extern __shared__ char sm[];
    const uint32_t s0 = smem_u32(sm);
    const int tid = threadIdx.x, lane = tid & 31, warp = tid >> 5;
    const int lbase = blockIdx.x * 128, nbase = blockIdx.y * 128, b = blockIdx.z;

    float* sIndot = (float*)(sm + G1_INDOT);
    float* sMbias = (float*)(sm + G1_MBIAS);
    if (tid < 128) {
        sIndot[tid] = g_indot[b * LL + lbase + tid];
        sMbias[tid] = g_mbias[b * MM + nbase + tid];
    }

    float acc[2][8][4];
    #pragma unroll
    for (int mt = 0; mt < 2; mt++)
        #pragma unroll
        for (int nt = 0; nt < 8; nt++)
            #pragma unroll
            for (int q = 0; q < 4; q++) acc[mt][nt][q] = 0.f;

    const int warpM = (warp >> 1) * 32, warpN = (warp & 1) * 64;
    const int g = lane >> 3, lr = lane & 7, h = (lane >> 3) & 1;

    uint4 sah[4], sal[4], sbh[4], sbl[4];
    // prologue stage chunk 0
    #pragma unroll
    for (int j = 0; j < 4; j++) {
        int idx = tid + j * 256, row = idx >> 3, c8 = (idx & 7) * 8;
        size_t ra = (size_t)(b * LL + lbase + row) * DD + c8;
        size_t rb = (size_t)(b * MM + nbase + row) * DD + c8;
        sah[j] = *(const uint4*)(g_xs_hi + ra);  sal[j] = *(const uint4*)(g_xs_lo + ra);
        sbh[j] = *(const uint4*)(g_mem_hi + rb); sbl[j] = *(const uint4*)(g_mem_lo + rb);
    }

    for (int kc = 0; kc < 4; kc++) {
        __syncthreads();   // prior MMA done reading smem
        #pragma unroll
        for (int j = 0; j < 4; j++) {
            int idx = tid + j * 256, row = idx >> 3, c8 = (idx & 7) * 8;
            uint32_t o = (uint32_t)(row * STRA + c8) * 2;
            *(uint4*)(sm + G1_SA_HI + o) = sah[j];
            *(uint4*)(sm + G1_SA_LO + o) = sal[j];
            *(uint4*)(sm + G1_SB_HI + o) = sbh[j];
            *(uint4*)(sm + G1_SB_LO + o) = sbl[j];
        }
        __syncthreads();
        if (kc < 3) {   // stage next chunk; overlaps the MMAs below
            int kk = (kc + 1) * 64;
            #pragma unroll
            for (int j = 0; j < 4; j++) {
                int idx = tid + j * 256, row = idx >> 3, c8 = (idx & 7) * 8;
                size_t ra = (size_t)(b * LL + lbase + row) * DD + kk + c8;
                size_t rb = (size_t)(b * MM + nbase + row) * DD + kk + c8;
                sah[j] = *(const uint4*)(g_xs_hi + ra);  sal[j] = *(const uint4*)(g_xs_lo + ra);
                sbh[j] = *(const uint4*)(g_mem_hi + rb); sbl[j] = *(const uint4*)(g_mem_lo + rb);
            }
        }
        #pragma unroll
        for (int ks = 0; ks < 4; ks++) {
            uint32_t aoff = s0 + 2u * ((warpM + (g & 1) * 8 + lr) * STRA + ks * 16 + (g >> 1) * 8);
            uint32_t boff = s0 + 2u * ((warpN + lr) * STRA + ks * 16 + h * 8);
            uint32_t ah[2][4], al[2][4], bh[8][2], bl[8][2];
            ldsm_x4(ah[0], aoff + G1_SA_HI);
            ldsm_x4(ah[1], aoff + G1_SA_HI + 16 * STRA * 2);
            #pragma unroll
            for (int nt = 0; nt < 8; nt++) ldsm_x2(bh[nt], boff + G1_SB_HI + nt * 8 * STRA * 2);
            #pragma unroll
            for (int mt = 0; mt < 2; mt++)
                #pragma unroll
                for (int nt = 0; nt < 8; nt++) mma16816(acc[mt][nt], ah[mt], bh[nt]);
            #pragma unroll
            for (int nt = 0; nt < 8; nt++) ldsm_x2(bl[nt], boff + G1_SB_LO + nt * 8 * STRA * 2);
            #pragma unroll
            for (int mt = 0; mt < 2; mt++)
                #pragma unroll
                for (int nt = 0; nt < 8; nt++) mma16816(acc[mt][nt], ah[mt], bl[nt]);
            ldsm_x4(al[0], aoff + G1_SA_LO);
            ldsm_x4(al[1], aoff + G1_SA_LO + 16 * STRA * 2);
            #pragma unroll
            for (int mt = 0; mt < 2; mt++)
                #pragma unroll
                for (int nt = 0; nt < 8; nt++) mma16816(acc[mt][nt], al[mt], bh[nt]);
        }
    }

    // ---------- epilogue: add biases (into acc), store att ----------
    const int r0 = lane >> 2, c0 = 2 * (lane & 3);
    #pragma unroll
    for (int mt = 0; mt < 2; mt++) {
        #pragma unroll
        for (int nt = 0; nt < 8; nt++) {
            int lrow = warpM + mt * 16 + r0;
            int lcol = warpN + nt * 8 + c0;
            float bi0 = sMbias[lcol], bi1 = sMbias[lcol + 1];
            acc[mt][nt][0] += sIndot[lrow] + bi0;
            acc[mt][nt][1] += sIndot[lrow] + bi1;
            acc[mt][nt][2] += sIndot[lrow + 8] + bi0;
            acc[mt][nt][3] += sIndot[lrow + 8] + bi1;
            size_t base = ((size_t)(b * LL + lbase + lrow)) * MM + nbase + lcol;
            *(float2*)(g_att + base)          = make_float2(acc[mt][nt][0], acc[mt][nt][1]);
            *(float2*)(g_att + base + 8 * MM) = make_float2(acc[mt][nt][2], acc[mt][nt][3]);
        }
    }

    // ---------- partial row stats over this 128-col tile ----------
    float pm[2][2], pz[2][2];
    #pragma unroll
    for (int mt = 0; mt < 2; mt++) {
        pm[mt][0] = -INFINITY; pm[mt][1] = -INFINITY;
        #pragma unroll
        for (int nt = 0; nt < 8; nt++) {
            pm[mt][0] = fmaxf(pm[mt][0], fmaxf(acc[mt][nt][0], acc[mt][nt][1]));
            pm[mt][1] = fmaxf(pm[mt][1], fmaxf(acc[mt][nt][2], acc[mt][nt][3]));
        }
    }
    #pragma unroll
    for (int x = 1; x <= 2; x <<= 1)
        #pragma unroll
        for (int mt = 0; mt < 2; mt++)
            #pragma unroll
            for (int hf = 0; hf < 2; hf++)
                pm[mt][hf] = fmaxf(pm[mt][hf], __shfl_xor_sync(0xffffffffu, pm[mt][hf], x));
    #pragma unroll
    for (int mt = 0; mt < 2; mt++) {
        pz[mt][0] = 0.f; pz[mt][1] = 0.f;
        #pragma unroll
        for (int nt = 0; nt < 8; nt++) {
            pz[mt][0] += __expf(acc[mt][nt][0] - pm[mt][0]) + __expf(acc[mt][nt][1] - pm[mt][0]);
            pz[mt][1] += __expf(acc[mt][nt][2] - pm[mt][1]) + __expf(acc[mt][nt][3] - pm[mt][1]);
        }
    }
    #pragma unroll
    for (int x = 1; x <= 2; x <<= 1)
        #pragma unroll
        for (int mt = 0; mt < 2; mt++)
            #pragma unroll
            for (int hf = 0; hf < 2; hf++)
                pz[mt][hf] += __shfl_xor_sync(0xffffffffu, pz[mt][hf], x);

    float* sPm = (float*)(sm + G1_PMAX);
    float* sPz = (float*)(sm + G1_PSUM);
    int wn = warpN >> 6;
    __syncthreads();
    if ((lane & 3) == 0) {
        #pragma unroll
        for (int mt = 0; mt < 2; mt++)
            #pragma unroll
            for (int hf = 0; hf < 2; hf++) {
                int row = warpM + mt * 16 + (lane >> 2) + hf * 8;
                sPm[row * 2 + wn] = pm[mt][hf];
                sPz[row * 2 + wn] = pz[mt][hf];
            }
    }
    __syncthreads();
    if (tid < 128) {
        float m0 = sPm[tid * 2], m1 = sPm[tid * 2 + 1];
        float m = fmaxf(m0, m1);
        float z = sPz[tid * 2] * __expf(m0 - m) + sPz[tid * 2 + 1] * __expf(m1 - m);
        size_t o = (size_t)(b * LL + lbase + tid) * 16 + blockIdx.y;
        g_pmax[o] = m; g_psum[o] = z;
    }
}

// ---------------------------------------------------------------------------
// combine: per row, 16 partials -> rowmax, rowinv
// ---------------------------------------------------------------------------
__global__ void combine_kernel() {
    int row = blockIdx.x * 256 + threadIdx.x;
    const float* pm = g_pmax + (size_t)row * 16;
    const float* pz = g_psum + (size_t)row * 16;
    float m = -INFINITY;
    #pragma unroll
    for (int t = 0; t < 16; t++) m = fmaxf(m, pm[t]);
    float z = 0.f;
    #pragma unroll
    for (int t = 0; t < 16; t++) z += pz[t] * __expf(pm[t] - m);
    g_rowmax[row] = m;
    g_rowinv[row] = 1.0f / z;
}

// ---------------------------------------------------------------------------
// GEMM2: output_one = softmax(att).mem   (CTA 64L x 256D, inline exp)
// grid (L/64, B); warp tile 32x64 (2M x 4N warps)
// ---------------------------------------------------------------------------
__global__ void __launch_bounds__(256) gemm2_kernel(const float* __restrict__ inp,
                                                    float* __restrict__ out) {
    extern __shared__ char sm[];
    const uint32_t s0 = smem_u32(sm);
    const int tid = threadIdx.x, lane = tid & 31, warp = tid >> 5;
    const int lbase = blockIdx.x * 64, b = blockIdx.y;

    float* sRmax = (float*)(sm + G2_RMAX);
    float* sRinv = (float*)(sm + G2_RINV);
    if (tid < 64) {
        sRmax[tid] = g_rowmax[b * LL + lbase + tid];
        sRinv[tid] = g_rowinv[b * LL + lbase + tid];
    }
    __syncthreads();

    float acc[2][8][4];
    #pragma unroll
    for (int mt = 0; mt < 2; mt++)
        #pragma unroll
        for (int nt = 0; nt < 8; nt++)
            #pragma unroll
            for (int q = 0; q < 4; q++) acc[mt][nt][q] = 0.f;

    const int warpM = (warp >> 2) * 32, warpN = (warp & 3) * 64;
    const int g = lane >> 3, lr = lane & 7, h = (lane >> 3) & 1;
    const float* attBase = g_att + ((size_t)(b * LL + lbase)) * MM;
    const size_t memRow = (size_t)b * MM * DD;

    float4 sa[4];
    uint4 sbh[8], sbl[8];
    // prologue stage chunk 0
    #pragma unroll
    for (int j = 0; j < 4; j++) {
        int idx = tid + j * 256, row = idx >> 4, c4 = (idx & 15) * 4;
        sa[j] = *(const float4*)(attBase + (size_t)row * MM + c4);
    }
    #pragma unroll
    for (int j = 0; j < 8; j++) {
        int idx = tid + j * 256, row = idx >> 5, c = (idx & 31) * 8;
        size_t rb = memRow + (size_t)row * DD + c;
        sbh[j] = *(const uint4*)(g_mem_hi + rb);
        sbl[j] = *(const uint4*)(g_mem_lo + rb);
    }

    for (int kc = 0; kc < 32; kc++) {
        __syncthreads();
        #pragma unroll
        for (int j = 0; j < 4; j++) {
            int idx = tid + j * 256, row = idx >> 4, c4 = (idx & 15) * 4;
            float mx = sRmax[row], iz = sRinv[row];
            float4 v = sa[j];
            v.x = __expf(v.x - mx) * iz; v.y = __expf(v.y - mx) * iz;
            v.z = __expf(v.z - mx) * iz; v.w = __expf(v.w - mx) * iz;
            uint2 hi, lo;
            split4(v, hi, lo);
            uint32_t o = (uint32_t)(row * STRA + c4) * 2;
            *(uint2*)(sm + G2_SA_HI + o) = hi;
            *(uint2*)(sm + G2_SA_LO + o) = lo;
        }
        #pragma unroll
        for (int j = 0; j < 8; j++) {
            int idx = tid + j * 256, row = idx >> 5, c = (idx & 31) * 8;
            uint32_t o = (uint32_t)(row * STRB2 + c) * 2;
            *(uint4*)(sm + G2_SB_HI + o) = sbh[j];
            *(uint4*)(sm + G2_SB_LO + o) = sbl[j];
        }
        __syncthreads();
        if (kc < 31) {
            int kk = (kc + 1) * 64;
            #pragma unroll
            for (int j = 0; j < 4; j++) {
                int idx = tid + j * 256, row = idx >> 4, c4 = (idx & 15) * 4;
                sa[j] = *(const float4*)(attBase + (size_t)row * MM + kk + c4);
            }
            #pragma unroll
            for (int j = 0; j < 8; j++) {
                int idx = tid + j * 256, row = idx >> 5, c = (idx & 31) * 8;
                size_t rb = memRow + (size_t)(kk + row) * DD + c;
                sbh[j] = *(const uint4*)(g_mem_hi + rb);
                sbl[j] = *(const uint4*)(g_mem_lo + rb);
            }
        }
        #pragma unroll
        for (int ks = 0; ks < 4; ks++) {
            uint32_t aoff = s0 + 2u * ((warpM + (g & 1) * 8 + lr) * STRA + ks * 16 + (g >> 1) * 8);
            int kk = ks * 16 + h * 8 + lr;
            uint32_t boff = s0 + 2u * (kk * STRB2 + warpN);
            uint32_t ah[2][4], al[2][4], bh[8][2], bl[8][2];
            ldsm_x4(ah[0], aoff + G2_SA_HI);
            ldsm_x4(ah[1], aoff + G2_SA_HI + 16 * STRA * 2);
            #pragma unroll
            for (int nt = 0; nt < 8; nt++) ldsm_x2t(bh[nt], boff + G2_SB_HI + nt * 16);
            #pragma unroll
            for (int mt = 0; mt < 2; mt++)
                #pragma unroll
                for (int nt = 0; nt < 8; nt++) mma16816(acc[mt][nt], ah[mt], bh[nt]);
            #pragma unroll
            for (int nt = 0; nt < 8; nt++) ldsm_x2t(bl[nt], boff + G2_SB_LO + nt * 16);
            #pragma unroll
            for (int mt = 0; mt < 2; mt++)
                #pragma unroll
                for (int nt = 0; nt < 8; nt++) mma16816(acc[mt][nt], ah[mt], bl[nt]);
            ldsm_x4(al[0], aoff + G2_SA_LO);
            ldsm_x4(al[1], aoff + G2_SA_LO + 16 * STRA * 2);
            #pragma unroll
            for (int mt = 0; mt < 2; mt++)
                #pragma unroll
                for (int nt = 0; nt < 8; nt++) mma16816(acc[mt][nt], al[mt], bh[nt]);
        }
    }

    // epilogue: write input / output_one / input*output_one
    const int r0 = lane >> 2, c0 = 2 * (lane & 3);
    #pragma unroll
    for (int mt = 0; mt < 2; mt++) {
        #pragma unroll
        for (int nt = 0; nt < 8; nt++) {
            int lrow = warpM + mt * 16 + r0;
            int d = warpN + nt * 8 + c0;
            #pragma unroll
            for (int half = 0; half < 2; half++) {
                size_t grow = (size_t)(b * LL + lbase + lrow + half * 8);
                float2 xv = *(const float2*)(inp + grow * DD + d);
                float2 o1 = make_float2(acc[mt][nt][half * 2], acc[mt][nt][half * 2 + 1]);
                float* ob = out + grow * OD;
                *(float2*)(ob + d)          = xv;
                *(float2*)(ob + DD + d)     = o1;
                *(float2*)(ob + 2 * DD + d) = make_float2(xv.x * o1.x, xv.y * o1.y);
            }
        }
    }
}

// ---------------------------------------------------------------------------
// output_two path
// ---------------------------------------------------------------------------
__global__ void c0_kernel() {
    int b = blockIdx.x, tid = threadIdx.x;
    __shared__ float red[256];
    float m = -INFINITY;
    for (int l = tid; l < LL; l += 256) m = fmaxf(m, g_rowmax[b * LL + l]);
    red[tid] = m; __syncthreads();
    for (int s = 128; s; s >>= 1) { if (tid < s) red[tid] = fmaxf(red[tid], red[tid + s]); __syncthreads(); }
    float gmax = red[0]; __syncthreads();
    float z = 0.f;
    for (int l = tid; l < LL; l += 256) z += expf(g_rowmax[b * LL + l] - gmax);
    red[tid] = z; __syncthreads();
    for (int s = 128; s; s >>= 1) { if (tid < s) red[tid] += red[tid + s]; __syncthreads(); }
    if (tid == 0) { g_gmax[b] = gmax; g_Z[b] = red[0]; }
}

__global__ void c1_kernel(const float* __restrict__ inp) {
    int b = blockIdx.y, sblk = blockIdx.x, tid = threadIdx.x;
    __shared__ float ws[256];
    float gmax = g_gmax[b], invZ = 1.0f / g_Z[b];
    int l0 = sblk * 256;
    ws[tid] = expf(g_rowmax[b * LL + l0 + tid] - gmax) * invZ;
    __syncthreads();
    float acc = 0.f;
    const float* xp = inp + ((size_t)b * LL + l0) * DD + tid;
    #pragma unroll 4
    for (int l = 0; l < 256; l++) acc = fmaf(ws[l], xp[(size_t)l * DD], acc);
    g_o2part[(b * 8 + sblk) * DD + tid] = acc;
}

__global__ void c2_kernel(float* __restrict__ out) {
    int b = blockIdx.y, tid = threadIdx.x;
    __shared__ float o2s[256];
    float a = 0.f;
    #pragma unroll
    for (int s = 0; s < 8; s++) a += g_o2part[(b * 8 + s) * DD + tid];
    o2s[tid] = a; __syncthreads();
    int lbase = blockIdx.x * 16;
    for (int rr = 0; rr < 16; rr++) {
        size_t ob = ((size_t)(b * LL + lbase + rr)) * OD;
        out[ob + 3 * DD + tid] = o2s[tid] * out[ob + DD + tid];
    }
}

// ---------------------------------------------------------------------------
extern "C" void kernel_launch(void* const* d_in, const int* in_sizes, int n_in,
                              void* d_out, int out_size) {
    const float* inp  = (const float*)d_in[0];
    const float* mem  = (const float*)d_in[1];
    const float* mask = (const float*)d_in[2];
    const float* wi   = (const float*)d_in[3];
    const float* wm   = (const float*)d_in[4];
    const float* ds   = (const float*)d_in[5];
    float* out = (float*)d_out;

    cudaFuncSetAttribute(gemm1_kernel, cudaFuncAttributeMaxDynamicSharedMemorySize, G1_SMEM);
    cudaFuncSetAttribute(gemm2_kernel, cudaFuncAttributeMaxDynamicSharedMemorySize, G2_SMEM);

    dots_kernel<<<(BB * (LL + MM)) / 8, 256>>>(inp, mem, mask, wi, wm);
    conv_kernel<<<2 * (BB * LL * DD / 4) / 256, 256>>>(inp, mem, ds);
    gemm1_kernel<<<dim3(LL / 128, MM / 128, BB), 256, G1_SMEM>>>();
    combine_kernel<<<BB * LL / 256, 256>>>();
    gemm2_kernel<<<dim3(LL / 64, BB), 256, G2_SMEM>>>(inp, out);
    c0_kernel<<<BB, 256>>>();
    c1_kernel<<<dim3(LL / 256, BB), 256>>>(inp);
    c2_kernel<<<dim3(LL / 16, BB), 256>>>(out);
}

// round 5
// speedup vs baseline: 3.6185x; 1.0239x over previous
#include <cuda_runtime.h>
#include <cuda_bf16.h>
#include <math.h>
#include <stdint.h>

#define BB 8
#define LL 2048
#define MM 2048
#define DD 256
#define OD 1024

// ---------------------------------------------------------------------------
// Scratch (device globals)
// ---------------------------------------------------------------------------
__device__ unsigned int g_p[(size_t)BB * LL * MM];            // packed p hi/lo bf16, 134 MB
__device__ __nv_bfloat16 g_xs_hi[BB*LL*DD],  g_xs_lo[BB*LL*DD];
__device__ __nv_bfloat16 g_mem_hi[BB*MM*DD], g_mem_lo[BB*MM*DD];
__device__ float g_indot[BB*LL], g_mbias[BB*MM];
__device__ float g_pmax[BB*LL*16], g_psum[BB*LL*16];
__device__ float g_pscale[BB*LL*16];
__device__ float g_rowmax[BB*LL];
__device__ float g_gmax[BB], g_Z[BB], g_o2part[BB*32*DD];

// ---------------------------------------------------------------------------
// PTX helpers
// ---------------------------------------------------------------------------
__device__ __forceinline__ uint32_t smem_u32(const void* p) {
    uint32_t a;
    asm("{ .reg .u64 t; cvta.to.shared.u64 t, %1; cvt.u32.u64 %0, t; }" : "=r"(a) : "l"(p));
    return a;
}
__device__ __forceinline__ void ldsm_x4(uint32_t* r, uint32_t a) {
    asm volatile("ldmatrix.sync.aligned.m8n8.x4.shared.b16 {%0,%1,%2,%3}, [%4];"
        : "=r"(r[0]), "=r"(r[1]), "=r"(r[2]), "=r"(r[3]) : "r"(a));
}
__device__ __forceinline__ void ldsm_x2(uint32_t* r, uint32_t a) {
    asm volatile("ldmatrix.sync.aligned.m8n8.x2.shared.b16 {%0,%1}, [%2];"
        : "=r"(r[0]), "=r"(r[1]) : "r"(a));
}
__device__ __forceinline__ void ldsm_x2t(uint32_t* r, uint32_t a) {
    asm volatile("ldmatrix.sync.aligned.m8n8.x2.trans.shared.b16 {%0,%1}, [%2];"
        : "=r"(r[0]), "=r"(r[1]) : "r"(a));
}
__device__ __forceinline__ void mma16816(float* d, const uint32_t* a, const uint32_t* b) {
    asm volatile("mma.sync.aligned.m16n8k16.row.col.f32.bf16.bf16.f32 "
        "{%0,%1,%2,%3}, {%4,%5,%6,%7}, {%8,%9}, {%0,%1,%2,%3};"
        : "+f"(d[0]), "+f"(d[1]), "+f"(d[2]), "+f"(d[3])
        : "r"(a[0]), "r"(a[1]), "r"(a[2]), "r"(a[3]), "r"(b[0]), "r"(b[1]));
}
__device__ __forceinline__ void split4(float4 v, uint2& hi, uint2& lo) {
    __nv_bfloat16 h0 = __float2bfloat16(v.x), h1 = __float2bfloat16(v.y);
    __nv_bfloat16 h2 = __float2bfloat16(v.z), h3 = __float2bfloat16(v.w);
    __nv_bfloat16 l0 = __float2bfloat16(v.x - __bfloat162float(h0));
    __nv_bfloat16 l1 = __float2bfloat16(v.y - __bfloat162float(h1));
    __nv_bfloat16 l2 = __float2bfloat16(v.z - __bfloat162float(h2));
    __nv_bfloat16 l3 = __float2bfloat16(v.w - __bfloat162float(h3));
    hi.x = (uint32_t)__bfloat16_as_ushort(h0) | ((uint32_t)__bfloat16_as_ushort(h1) << 16);
    hi.y = (uint32_t)__bfloat16_as_ushort(h2) | ((uint32_t)__bfloat16_as_ushort(h3) << 16);
    lo.x = (uint32_t)__bfloat16_as_ushort(l0) | ((uint32_t)__bfloat16_as_ushort(l1) << 16);
    lo.y = (uint32_t)__bfloat16_as_ushort(l2) | ((uint32_t)__bfloat16_as_ushort(l3) << 16);
}

// FFMA/ALU-only exp (no MUFU). Valid for x <= 0; rel err ~2e-6.
__device__ __forceinline__ float fast_exp(float x) {
    x = fmaxf(x, -80.0f);
    float y = x * 1.4426950408889634f;           // x * log2(e)
    float nf = y + 12582912.0f;                  // round-to-nearest via magic
    int   i  = __float_as_int(nf);
    float n  = nf - 12582912.0f;
    float f  = y - n;                            // f in [-0.5, 0.5]
    float p = 1.5403530e-4f;
    p = fmaf(p, f, 1.3333558e-3f);
    p = fmaf(p, f, 9.6181291e-3f);
    p = fmaf(p, f, 5.5504109e-2f);
    p = fmaf(p, f, 2.4022651e-1f);
    p = fmaf(p, f, 6.9314718e-1f);
    p = fmaf(p, f, 1.0f);
    return p * __int_as_float((i - 0x4B3FFF81) << 23);   // * 2^n
}

// pack p (fp32 in [0,1]) into bf16 hi/lo pair in one u32 (hi in low half)
__device__ __forceinline__ uint32_t packp(float p) {
    __nv_bfloat16 h = __float2bfloat16(p);
    __nv_bfloat16 l = __float2bfloat16(p - __bfloat162float(h));
    return (uint32_t)__bfloat16_as_ushort(h) | ((uint32_t)__bfloat16_as_ushort(l) << 16);
}
// unpack: value = hi + lo
__device__ __forceinline__ float unpackp(uint32_t w) {
    return __uint_as_float(w << 16) + __uint_as_float(w & 0xFFFF0000u);
}

// ---------------------------------------------------------------------------
// smem layout
// ---------------------------------------------------------------------------
#define STRA  72
#define STRB2 264

#define G1_SA_HI 0
#define G1_SA_LO 18432
#define G1_SB_HI 36864
#define G1_SB_LO 55296
#define G1_INDOT 73728
#define G1_MBIAS 74240
#define G1_PMAX  74752
#define G1_PSUM  75776
#define G1_SMEM  76800

#define G2_SA_HI  0
#define G2_SA_LO  9216
#define G2_SB_HI  18432
#define G2_SB_LO  52224
#define G2_SCALE  86016
#define G2_SMEM   90112

// ---------------------------------------------------------------------------
// dots
// ---------------------------------------------------------------------------
__global__ void dots_kernel(const float* __restrict__ inp, const float* __restrict__ mem,
                            const float* __restrict__ mask, const float* __restrict__ wi,
                            const float* __restrict__ wm) {
    int row = blockIdx.x * 8 + (threadIdx.x >> 5);
    int lane = threadIdx.x & 31;
    bool isMem = row >= BB * LL;
    int r = isMem ? row - BB * LL : row;
    const float* src = (isMem ? mem : inp) + (size_t)r * DD;
    const float* w = isMem ? wm : wi;
    float s = 0.f;
    #pragma unroll
    for (int k = 0; k < 8; k++) { int d = lane + 32 * k; s = fmaf(src[d], w[d], s); }
    #pragma unroll
    for (int o = 16; o; o >>= 1) s += __shfl_xor_sync(0xffffffffu, s, o);
    if (lane == 0) {
        if (isMem) g_mbias[r] = s - 1e30f * (1.0f - mask[r]);
        else       g_indot[r] = s;
    }
}

// ---------------------------------------------------------------------------
// conv: hi/lo bf16 split of xs = input*ds and memory
// ---------------------------------------------------------------------------
__global__ void conv_kernel(const float* __restrict__ inp, const float* __restrict__ mem,
                            const float* __restrict__ ds) {
    const int N4 = BB * LL * DD / 4;
    int i = blockIdx.x * 256 + threadIdx.x;
    bool isMem = i >= N4;
    int j = isMem ? i - N4 : i;
    float4 x = ((const float4*)(isMem ? mem : inp))[j];
    if (!isMem) {
        float4 s = ((const float4*)ds)[j & (DD / 4 - 1)];
        x.x *= s.x; x.y *= s.y; x.z *= s.z; x.w *= s.w;
    }
    uint2 hv, lv;
    split4(x, hv, lv);
    ((uint2*)(isMem ? g_mem_hi : g_xs_hi))[j] = hv;
    ((uint2*)(isMem ? g_mem_lo : g_xs_lo))[j] = lv;
}

// ---------------------------------------------------------------------------
// GEMM1: s = xs.mem^T + indot + mbias; store p = exp(s - tile_max) packed bf16;
// store per-(row,tile) max and sumexp. grid (L/128, M/128, B)
// ---------------------------------------------------------------------------
__global__ void __launch_bounds__(256) gemm1_kernel() {
    extern __shared__ char sm[];
    const uint32_t s0 = smem_u32(sm);
    const int tid = threadIdx.x, lane = tid & 31, warp = tid >> 5;
    const int lbase = blockIdx.x * 128, nbase = blockIdx.y * 128, b = blockIdx.z;

    float* sIndot = (float*)(sm + G1_INDOT);
    float* sMbias = (float*)(sm + G1_MBIAS);
    if (tid < 128) {
        sIndot[tid] = g_indot[b * LL + lbase + tid];
        sMbias[tid] = g_mbias[b * MM + nbase + tid];
    }

    float acc[2][8][4];
    #pragma unroll
    for (int mt = 0; mt < 2; mt++)
        #pragma unroll
        for (int nt = 0; nt < 8; nt++)
            #pragma unroll
            for (int q = 0; q < 4; q++) acc[mt][nt][q] = 0.f;

    const int warpM = (warp >> 1) * 32, warpN = (warp & 1) * 64;
    const int g = lane >> 3, lr = lane & 7, h = (lane >> 3) & 1;

    uint4 sah[4], sal[4], sbh[4], sbl[4];
    #pragma unroll
    for (int j = 0; j < 4; j++) {
        int idx = tid + j * 256, row = idx >> 3, c8 = (idx & 7) * 8;
        size_t ra = (size_t)(b * LL + lbase + row) * DD + c8;
        size_t rb = (size_t)(b * MM + nbase + row) * DD + c8;
        sah[j] = *(const uint4*)(g_xs_hi + ra);  sal[j] = *(const uint4*)(g_xs_lo + ra);
        sbh[j] = *(const uint4*)(g_mem_hi + rb); sbl[j] = *(const uint4*)(g_mem_lo + rb);
    }

    for (int kc = 0; kc < 4; kc++) {
        __syncthreads();
        #pragma unroll
        for (int j = 0; j < 4; j++) {
            int idx = tid + j * 256, row = idx >> 3, c8 = (idx & 7) * 8;
            uint32_t o = (uint32_t)(row * STRA + c8) * 2;
            *(uint4*)(sm + G1_SA_HI + o) = sah[j];
            *(uint4*)(sm + G1_SA_LO + o) = sal[j];
            *(uint4*)(sm + G1_SB_HI + o) = sbh[j];
            *(uint4*)(sm + G1_SB_LO + o) = sbl[j];
        }
        __syncthreads();
        if (kc < 3) {
            int kk = (kc + 1) * 64;
            #pragma unroll
            for (int j = 0; j < 4; j++) {
                int idx = tid + j * 256, row = idx >> 3, c8 = (idx & 7) * 8;
                size_t ra = (size_t)(b * LL + lbase + row) * DD + kk + c8;
                size_t rb = (size_t)(b * MM + nbase + row) * DD + kk + c8;
                sah[j] = *(const uint4*)(g_xs_hi + ra);  sal[j] = *(const uint4*)(g_xs_lo + ra);
                sbh[j] = *(const uint4*)(g_mem_hi + rb); sbl[j] = *(const uint4*)(g_mem_lo + rb);
            }
        }
        #pragma unroll
        for (int ks = 0; ks < 4; ks++) {
            uint32_t aoff = s0 + 2u * ((warpM + (g & 1) * 8 + lr) * STRA + ks * 16 + (g >> 1) * 8);
            uint32_t boff = s0 + 2u * ((warpN + lr) * STRA + ks * 16 + h * 8);
            uint32_t ah[2][4], al[2][4], bh[8][2], bl[8][2];
            ldsm_x4(ah[0], aoff + G1_SA_HI);
            ldsm_x4(ah[1], aoff + G1_SA_HI + 16 * STRA * 2);
            #pragma unroll
            for (int nt = 0; nt < 8; nt++) ldsm_x2(bh[nt], boff + G1_SB_HI + nt * 8 * STRA * 2);
            #pragma unroll
            for (int mt = 0; mt < 2; mt++)
                #pragma unroll
                for (int nt = 0; nt < 8; nt++) mma16816(acc[mt][nt], ah[mt], bh[nt]);
            #pragma unroll
            for (int nt = 0; nt < 8; nt++) ldsm_x2(bl[nt], boff + G1_SB_LO + nt * 8 * STRA * 2);
            #pragma unroll
            for (int mt = 0; mt < 2; mt++)
                #pragma unroll
                for (int nt = 0; nt < 8; nt++) mma16816(acc[mt][nt], ah[mt], bl[nt]);
            ldsm_x4(al[0], aoff + G1_SA_LO);
            ldsm_x4(al[1], aoff + G1_SA_LO + 16 * STRA * 2);
            #pragma unroll
            for (int mt = 0; mt < 2; mt++)
                #pragma unroll
                for (int nt = 0; nt < 8; nt++) mma16816(acc[mt][nt], al[mt], bh[nt]);
        }
    }

    // ---------- epilogue: biases, per-warp max, tile max, p store, sums ----------
    const int r0 = lane >> 2, c0 = 2 * (lane & 3);
    #pragma unroll
    for (int mt = 0; mt < 2; mt++)
        #pragma unroll
        for (int nt = 0; nt < 8; nt++) {
            int lrow = warpM + mt * 16 + r0;
            int lcol = warpN + nt * 8 + c0;
            float bi0 = sMbias[lcol], bi1 = sMbias[lcol + 1];
            acc[mt][nt][0] += sIndot[lrow] + bi0;
            acc[mt][nt][1] += sIndot[lrow] + bi1;
            acc[mt][nt][2] += sIndot[lrow + 8] + bi0;
            acc[mt][nt][3] += sIndot[lrow + 8] + bi1;
        }

    float pm[2][2];
    #pragma unroll
    for (int mt = 0; mt < 2; mt++) {
        pm[mt][0] = -INFINITY; pm[mt][1] = -INFINITY;
        #pragma unroll
        for (int nt = 0; nt < 8; nt++) {
            pm[mt][0] = fmaxf(pm[mt][0], fmaxf(acc[mt][nt][0], acc[mt][nt][1]));
            pm[mt][1] = fmaxf(pm[mt][1], fmaxf(acc[mt][nt][2], acc[mt][nt][3]));
        }
    }
    #pragma unroll
    for (int x = 1; x <= 2; x <<= 1)
        #pragma unroll
        for (int mt = 0; mt < 2; mt++)
            #pragma unroll
            for (int hf = 0; hf < 2; hf++)
                pm[mt][hf] = fmaxf(pm[mt][hf], __shfl_xor_sync(0xffffffffu, pm[mt][hf], x));

    float* sPm = (float*)(sm + G1_PMAX);
    float* sPz = (float*)(sm + G1_PSUM);
    int wn = warpN >> 6;
    __syncthreads();   // operand smem reads all done before reuse of barrier
    if ((lane & 3) == 0) {
        #pragma unroll
        for (int mt = 0; mt < 2; mt++)
            #pragma unroll
            for (int hf = 0; hf < 2; hf++) {
                int row = warpM + mt * 16 + (lane >> 2) + hf * 8;
                sPm[row * 2 + wn] = pm[mt][hf];
            }
    }
    __syncthreads();

    float tm[2][2];
    #pragma unroll
    for (int mt = 0; mt < 2; mt++)
        #pragma unroll
        for (int hf = 0; hf < 2; hf++) {
            int row = warpM + mt * 16 + r0 + hf * 8;
            tm[mt][hf] = fmaxf(sPm[row * 2], sPm[row * 2 + 1]);
        }

    float pz[2][2] = {{0.f, 0.f}, {0.f, 0.f}};
    #pragma unroll
    for (int mt = 0; mt < 2; mt++) {
        #pragma unroll
        for (int nt = 0; nt < 8; nt++) {
            int lrow = warpM + mt * 16 + r0;
            int lcol = warpN + nt * 8 + c0;
            float p0 = fast_exp(acc[mt][nt][0] - tm[mt][0]);
            float p1 = fast_exp(acc[mt][nt][1] - tm[mt][0]);
            float p2 = fast_exp(acc[mt][nt][2] - tm[mt][1]);
            float p3 = fast_exp(acc[mt][nt][3] - tm[mt][1]);
            pz[mt][0] += p0 + p1;
            pz[mt][1] += p2 + p3;
            size_t base = ((size_t)(b * LL + lbase + lrow)) * MM + nbase + lcol;
            *(uint2*)(g_p + base)          = make_uint2(packp(p0), packp(p1));
            *(uint2*)(g_p + base + 8 * MM) = make_uint2(packp(p2), packp(p3));
        }
    }
    #pragma unroll
    for (int x = 1; x <= 2; x <<= 1)
        #pragma unroll
        for (int mt = 0; mt < 2; mt++)
            #pragma unroll
            for (int hf = 0; hf < 2; hf++)
                pz[mt][hf] += __shfl_xor_sync(0xffffffffu, pz[mt][hf], x);
    if ((lane & 3) == 0) {
        #pragma unroll
        for (int mt = 0; mt < 2; mt++)
            #pragma unroll
            for (int hf = 0; hf < 2; hf++) {
                int row = warpM + mt * 16 + (lane >> 2) + hf * 8;
                sPz[row * 2 + wn] = pz[mt][hf];
            }
    }
    __syncthreads();
    if (tid < 128) {
        float m = fmaxf(sPm[tid * 2], sPm[tid * 2 + 1]);
        float z = sPz[tid * 2] + sPz[tid * 2 + 1];
        size_t o = (size_t)(b * LL + lbase + tid) * 16 + blockIdx.y;
        g_pmax[o] = m; g_psum[o] = z;
    }
}

// ---------------------------------------------------------------------------
// combine: per row: global max, 1/Z, and per-tile rescale factors
// ---------------------------------------------------------------------------
__global__ void combine_kernel() {
    int row = blockIdx.x * 256 + threadIdx.x;
    const float* pm = g_pmax + (size_t)row * 16;
    const float* pz = g_psum + (size_t)row * 16;
    float m = -INFINITY;
    #pragma unroll
    for (int t = 0; t < 16; t++) m = fmaxf(m, pm[t]);
    float z = 0.f;
    #pragma unroll
    for (int t = 0; t < 16; t++) z += pz[t] * fast_exp(pm[t] - m);
    float inv = 1.0f / z;
    g_rowmax[row] = m;
    #pragma unroll
    for (int t = 0; t < 16; t++)
        g_pscale[(size_t)row * 16 + t] = fast_exp(pm[t] - m) * inv;
}

// ---------------------------------------------------------------------------
// GEMM2: output_one = (p * scale) . mem   (no exp here at all)
// grid (L/64, B); CTA 64L x 256D; warp tile 32x64
// ---------------------------------------------------------------------------
__global__ void __launch_bounds__(256) gemm2_kernel(const float* __restrict__ inp,
                                                    float* __restrict__ out) {
    extern __shared__ char sm[];
    const uint32_t s0 = smem_u32(sm);
    const int tid = threadIdx.x, lane = tid & 31, warp = tid >> 5;
    const int lbase = blockIdx.x * 64, b = blockIdx.y;

    float* sScale = (float*)(sm + G2_SCALE);
    for (int i = tid; i < 64 * 16; i += 256)
        sScale[i] = g_pscale[(size_t)(b * LL + lbase + (i >> 4)) * 16 + (i & 15)];

    float acc[2][8][4];
    #pragma unroll
    for (int mt = 0; mt < 2; mt++)
        #pragma unroll
        for (int nt = 0; nt < 8; nt++)
            #pragma unroll
            for (int q = 0; q < 4; q++) acc[mt][nt][q] = 0.f;

    const int warpM = (warp >> 2) * 32, warpN = (warp & 3) * 64;
    const int g = lane >> 3, lr = lane & 7, h = (lane >> 3) & 1;
    const unsigned int* pBase = g_p + ((size_t)(b * LL + lbase)) * MM;
    const size_t memRow = (size_t)b * MM * DD;

    uint4 sa[4];
    uint4 sbh[8], sbl[8];
    #pragma unroll
    for (int j = 0; j < 4; j++) {
        int idx = tid + j * 256, row = idx >> 4, c4 = (idx & 15) * 4;
        sa[j] = *(const uint4*)(pBase + (size_t)row * MM + c4);
    }
    #pragma unroll
    for (int j = 0; j < 8; j++) {
        int idx = tid + j * 256, row = idx >> 5, c = (idx & 31) * 8;
        size_t rb = memRow + (size_t)row * DD + c;
        sbh[j] = *(const uint4*)(g_mem_hi + rb);
        sbl[j] = *(const uint4*)(g_mem_lo + rb);
    }

    for (int kc = 0; kc < 32; kc++) {
        __syncthreads();
        #pragma unroll
        for (int j = 0; j < 4; j++) {
            int idx = tid + j * 256, row = idx >> 4, c4 = (idx & 15) * 4;
            float sc = sScale[row * 16 + (kc >> 1)];
            uint4 u = sa[j];
            float4 v;
            v.x = unpackp(u.x) * sc;
            v.y = unpackp(u.y) * sc;
            v.z = unpackp(u.z) * sc;
            v.w = unpackp(u.w) * sc;
            uint2 hi, lo;
            split4(v, hi, lo);
            uint32_t o = (uint32_t)(row * STRA + c4) * 2;
            *(uint2*)(sm + G2_SA_HI + o) = hi;
            *(uint2*)(sm + G2_SA_LO + o) = lo;
        }
        #pragma unroll
        for (int j = 0; j < 8; j++) {
            int idx = tid + j * 256, row = idx >> 5, c = (idx & 31) * 8;
            uint32_t o = (uint32_t)(row * STRB2 + c) * 2;
            *(uint4*)(sm + G2_SB_HI + o) = sbh[j];
            *(uint4*)(sm + G2_SB_LO + o) = sbl[j];
        }
        __syncthreads();
        if (kc < 31) {
            int kk = (kc + 1) * 64;
            #pragma unroll
            for (int j = 0; j < 4; j++) {
                int idx = tid + j * 256, row = idx >> 4, c4 = (idx & 15) * 4;
                sa[j] = *(const uint4*)(pBase + (size_t)row * MM + kk + c4);
            }
            #pragma unroll
            for (int j = 0; j < 8; j++) {
                int idx = tid + j * 256, row = idx >> 5, c = (idx & 31) * 8;
                size_t rb = memRow + (size_t)(kk + row) * DD + c;
                sbh[j] = *(const uint4*)(g_mem_hi + rb);
                sbl[j] = *(const uint4*)(g_mem_lo + rb);
            }
        }
        #pragma unroll
        for (int ks = 0; ks < 4; ks++) {
            uint32_t aoff = s0 + 2u * ((warpM + (g & 1) * 8 + lr) * STRA + ks * 16 + (g >> 1) * 8);
            int kk = ks * 16 + h * 8 + lr;
            uint32_t boff = s0 + 2u * (kk * STRB2 + warpN);
            uint32_t ah[2][4], al[2][4], bh[8][2], bl[8][2];
            ldsm_x4(ah[0], aoff + G2_SA_HI);
            ldsm_x4(ah[1], aoff + G2_SA_HI + 16 * STRA * 2);
            #pragma unroll
            for (int nt = 0; nt < 8; nt++) ldsm_x2t(bh[nt], boff + G2_SB_HI + nt * 16);
            #pragma unroll
            for (int mt = 0; mt < 2; mt++)
                #pragma unroll
                for (int nt = 0; nt < 8; nt++) mma16816(acc[mt][nt], ah[mt], bh[nt]);
            #pragma unroll
            for (int nt = 0; nt < 8; nt++) ldsm_x2t(bl[nt], boff + G2_SB_LO + nt * 16);
            #pragma unroll
            for (int mt = 0; mt < 2; mt++)
                #pragma unroll
                for (int nt = 0; nt < 8; nt++) mma16816(acc[mt][nt], ah[mt], bl[nt]);
            ldsm_x4(al[0], aoff + G2_SA_LO);
            ldsm_x4(al[1], aoff + G2_SA_LO + 16 * STRA * 2);
            #pragma unroll
            for (int mt = 0; mt < 2; mt++)
                #pragma unroll
                for (int nt = 0; nt < 8; nt++) mma16816(acc[mt][nt], al[mt], bh[nt]);
        }
    }

    const int r0 = lane >> 2, c0 = 2 * (lane & 3);
    #pragma unroll
    for (int mt = 0; mt < 2; mt++) {
        #pragma unroll
        for (int nt = 0; nt < 8; nt++) {
            int lrow = warpM + mt * 16 + r0;
            int d = warpN + nt * 8 + c0;
            #pragma unroll
            for (int half = 0; half < 2; half++) {
                size_t grow = (size_t)(b * LL + lbase + lrow + half * 8);
                float2 xv = *(const float2*)(inp + grow * DD + d);
                float2 o1 = make_float2(acc[mt][nt][half * 2], acc[mt][nt][half * 2 + 1]);
                float* ob = out + grow * OD;
                *(float2*)(ob + d)          = xv;
                *(float2*)(ob + DD + d)     = o1;
                *(float2*)(ob + 2 * DD + d) = make_float2(xv.x * o1.x, xv.y * o1.y);
            }
        }
    }
}

// ---------------------------------------------------------------------------
// output_two path
// ---------------------------------------------------------------------------
__global__ void c0_kernel() {
    int b = blockIdx.x, tid = threadIdx.x;
    __shared__ float red[256];
    float m = -INFINITY;
    for (int l = tid; l < LL; l += 256) m = fmaxf(m, g_rowmax[b * LL + l]);
    red[tid] = m; __syncthreads();
    for (int s = 128; s; s >>= 1) { if (tid < s) red[tid] = fmaxf(red[tid], red[tid + s]); __syncthreads(); }
    float gmax = red[0]; __syncthreads();
    float z = 0.f;
    for (int l = tid; l < LL; l += 256) z += fast_exp(g_rowmax[b * LL + l] - gmax);
    red[tid] = z; __syncthreads();
    for (int s = 128; s; s >>= 1) { if (tid < s) red[tid] += red[tid + s]; __syncthreads(); }
    if (tid == 0) { g_gmax[b] = gmax; g_Z[b] = red[0]; }
}

__global__ void c1_kernel(const float* __restrict__ inp) {
    int b = blockIdx.y, sblk = blockIdx.x, tid = threadIdx.x;
    __shared__ float ws[64];
    int l0 = sblk * 64;
    if (tid < 64)
        ws[tid] = fast_exp(g_rowmax[b * LL + l0 + tid] - g_gmax[b]) * (1.0f / g_Z[b]);
    __syncthreads();
    float acc = 0.f;
    const float* xp = inp + ((size_t)b * LL + l0) * DD + tid;
    #pragma unroll 4
    for (int l = 0; l < 64; l++) acc = fmaf(ws[l], xp[(size_t)l * DD], acc);
    g_o2part[(b * 32 + sblk) * DD + tid] = acc;
}

__global__ void c2_kernel(float* __restrict__ out) {
    int b = blockIdx.y, tid = threadIdx.x;
    __shared__ float o2s[256];
    float a = 0.f;
    #pragma unroll
    for (int s = 0; s < 32; s++) a += g_o2part[(b * 32 + s) * DD + tid];
    o2s[tid] = a; __syncthreads();
    int lbase = blockIdx.x * 16;
    for (int rr = 0; rr < 16; rr++) {
        size_t ob = ((size_t)(b * LL + lbase + rr)) * OD;
        out[ob + 3 * DD + tid] = o2s[tid] * out[ob + DD + tid];
    }
}

// ---------------------------------------------------------------------------
extern "C" void kernel_launch(void* const* d_in, const int* in_sizes, int n_in,
                              void* d_out, int out_size) {
    const float* inp  = (const float*)d_in[0];
    const float* mem  = (const float*)d_in[1];
    const float* mask = (const float*)d_in[2];
    const float* wi   = (const float*)d_in[3];
    const float* wm   = (const float*)d_in[4];
    const float* ds   = (const float*)d_in[5];
    float* out = (float*)d_out;

    cudaFuncSetAttribute(gemm1_kernel, cudaFuncAttributeMaxDynamicSharedMemorySize, G1_SMEM);
    cudaFuncSetAttribute(gemm2_kernel, cudaFuncAttributeMaxDynamicSharedMemorySize, G2_SMEM);

    dots_kernel<<<(BB * (LL + MM)) / 8, 256>>>(inp, mem, mask, wi, wm);
    conv_kernel<<<2 * (BB * LL * DD / 4) / 256, 256>>>(inp, mem, ds);
    gemm1_kernel<<<dim3(LL / 128, MM / 128, BB), 256, G1_SMEM>>>();
    combine_kernel<<<BB * LL / 256, 256>>>();
    gemm2_kernel<<<dim3(LL / 64, BB), 256, G2_SMEM>>>(inp, out);
    c0_kernel<<<BB, 256>>>();
    c1_kernel<<<dim3(LL / 64, BB), 256>>>(inp);
    c2_kernel<<<dim3(LL / 16, BB), 256>>>(out);
}